// round 15
// baseline (speedup 1.0000x reference)
#include <cuda_runtime.h>
#include <cuda_fp16.h>
#include <cstdint>
#include <math.h>

#define BATCH    4
#define SEQLEN   4096
#define DIM      1024
#define HEADS    16
#define HEAD_DIM 64
#define SEG      64
#define NSEG     (SEQLEN / SEG)     // 64
#define KSEG     (SEG / 2)          // 32 (dilation 2)
#define KDIM     1024               // GEMM reduction dim
#define SCALE    0.125f             // 64^-0.5

// ---------------- scratch (static device globals; no allocs allowed) --------
__device__ __half g_Xh [BATCH * SEQLEN * DIM];               // fp16 x
__device__ __half g_Qh [BATCH * SEQLEN * DIM];               // hilbert-ordered, pre-scaled Q
__device__ __half g_KVh[BATCH * (SEQLEN / 2) * (2 * DIM)];   // dilated K|V (fp16)
__device__ __half g_Oh [BATCH * SEQLEN * DIM];               // attn out, original order
__device__ __half g_WqkvT[3 * DIM * DIM];                    // w_qkv^T fp16
__device__ __half g_WprojT[DIM * DIM];                       // w_proj^T fp16
__device__ int    g_qrow [BATCH * SEQLEN];
__device__ int    g_kvrow[BATCH * (SEQLEN / 2)];

// ---------------- helpers -----------------------------------------------------
__device__ __forceinline__ uint32_t smem_u32(const void* p) {
    uint32_t a;
    asm("{ .reg .u64 t; cvta.to.shared.u64 t, %1; cvt.u32.u64 %0, t; }" : "=r"(a) : "l"(p));
    return a;
}
__device__ __forceinline__ void cp_async16(uint32_t dst, const void* src) {
    asm volatile("cp.async.ca.shared.global [%0], [%1], 16;" :: "r"(dst), "l"(src));
}
__device__ __forceinline__ void cp_commit() {
    asm volatile("cp.async.commit_group;" ::: "memory");
}
template <int N>
__device__ __forceinline__ void cp_wait() {
    asm volatile("cp.async.wait_group %0;" :: "n"(N) : "memory");
}

// ---------------- fused prep: x->fp16, transposes, gather maps ---------------
__device__ __forceinline__ void transpose_body(const float* __restrict__ W,
                                               __half* __restrict__ Wt,
                                               int rows, int cols, int bxi, int byi,
                                               int tx, int ty)
{
    __shared__ float t[32][33];
    int bx = bxi * 32, by = byi * 32;
#pragma unroll
    for (int i = 0; i < 32; i += 8) {
        int y = by + ty + i, x = bx + tx;
        t[ty + i][tx] = W[(long)y * cols + x];
    }
    __syncthreads();
#pragma unroll
    for (int i = 0; i < 32; i += 8) {
        int y = bx + ty + i, x = by + tx;
        Wt[(long)y * rows + x] = __float2half_rn(t[tx][ty + i]);
    }
}

__global__ __launch_bounds__(256)
void prep_kernel(const float* __restrict__ x,
                 const float* __restrict__ w_qkv, const float* __restrict__ w_proj,
                 const int* __restrict__ hmap)
{
    const int id = blockIdx.x;
    if (id < 16384) {
        long t = (long)id * 256 + threadIdx.x;
        float4 v = ((const float4*)x)[t];
        __half2* dst = (__half2*)g_Xh + t * 2;
        dst[0] = __floats2half2_rn(v.x, v.y);
        dst[1] = __floats2half2_rn(v.z, v.w);
        return;
    }
    const int tx = threadIdx.x & 31, ty = threadIdx.x >> 5;
    if (id < 19456) {
        int i2 = id - 16384;
        transpose_body(w_qkv, g_WqkvT, DIM, 3 * DIM, i2 % 96, i2 / 96, tx, ty);
    } else if (id < 20480) {
        int i2 = id - 19456;
        transpose_body(w_proj, g_WprojT, DIM, DIM, i2 % 32, i2 / 32, tx, ty);
    } else {
        int t = (id - 20480) * 256 + threadIdx.x;
        if (t < BATCH * SEQLEN) {
            int b = t / SEQLEN, i = t % SEQLEN;
            g_qrow[t] = b * SEQLEN + hmap[i];
        }
        if (t < BATCH * (SEQLEN / 2)) {
            int b = t / (SEQLEN / 2), m = t % (SEQLEN / 2);
            int s = m / KSEG, j = m % KSEG;
            g_kvrow[t] = b * SEQLEN + hmap[s * SEG + 2 * j];
        }
    }
}

// ---------------- fp16 mma GEMM body -------------------------------------------
// CTA tile 128(M) x 256(N); 512 threads, 16 warps in 4(M)x4(N); warp tile 32x64.
// Keeps 16 warps/SM (latency hiding, R13-proven) while cutting fragment
// crossbar bytes/FLOP by 1.47x (R14 showed relief works; R14 failed on warps).
#define PADH     40
#define A_HALVES (128 * PADH)                 // 5120
#define B_HALVES (256 * PADH)                 // 10240
#define STAGE_BYTES ((A_HALVES + B_HALVES) * 2)  // 30720
#define NSTAGE   3
#define GSMEM    (NSTAGE * STAGE_BYTES)       // 92160
#define NCHUNK   (KDIM / 32)                  // 32
#define NTHREADS 512

extern __shared__ __align__(16) char dynsmem[];

template <typename OutT>
__device__ __forceinline__ void gemm_body(const __half* __restrict__ A,
                                          const __half* __restrict__ Bt,
                                          OutT* __restrict__ C,
                                          const int* __restrict__ rowidx,
                                          int ldc, int bx, int by, float alpha)
{
    __shared__ int rowid[128];

    const int tid   = threadIdx.x;
    const int wid   = tid >> 5;       // 0..15
    const int lane  = tid & 31;
    const int warp_m = wid >> 2;      // 0..3  (32 M-rows each)
    const int warp_n = wid & 3;       // 0..3  (64 N-cols each)
    const int bm = by * 128;
    const int bn = bx * 256;

    if (tid < 128) rowid[tid] = rowidx ? rowidx[bm + tid] : (bm + tid);
    __syncthreads();

    const uint32_t smb = smem_u32(dynsmem);

    auto issue = [&](int chunk) {
        const int s = chunk % NSTAGE;
        const int koff = chunk * 32;
        const uint32_t sA = smb + s * STAGE_BYTES;
        const uint32_t sB = sA + A_HALVES * 2;
        {                                              // A: 128 rows x 4 granules
            int row = tid >> 2, g = tid & 3;
            cp_async16(sA + row * (PADH * 2) + g * 16,
                       A + (long)rowid[row] * KDIM + koff + g * 8);
        }
#pragma unroll
        for (int i = 0; i < 2; i++) {                  // B: 256 rows x 4 granules
            int idx = tid + i * NTHREADS;
            int row = idx >> 2, g = idx & 3;
            cp_async16(sB + row * (PADH * 2) + g * 16,
                       Bt + (long)(bn + row) * KDIM + koff + g * 8);
        }
        cp_commit();
    };

    float acc[2][8][4];
#pragma unroll
    for (int i = 0; i < 2; i++)
#pragma unroll
        for (int j = 0; j < 8; j++)
#pragma unroll
            for (int r = 0; r < 4; r++) acc[i][j][r] = 0.0f;

    const int a_quad = lane >> 3;
    const int a_rowc = (a_quad & 1) * 8 + (lane & 7);
    const int a_kofs = (a_quad >> 1) * 8;
    const int b_rowc = ((lane >> 4) & 1) * 8 + (lane & 7);
    const int b_kofs = ((lane >> 3) & 1) * 8;

    issue(0); issue(1);

    for (int c = 0; c < NCHUNK; ++c) {
        if (c == NCHUNK - 1) cp_wait<0>();
        else                 cp_wait<1>();
        __syncthreads();
        if (c + 2 < NCHUNK) issue(c + 2);

        const uint32_t sA = smb + (c % NSTAGE) * STAGE_BYTES;
        const uint32_t sB = sA + A_HALVES * 2;

#pragma unroll
        for (int ks = 0; ks < 2; ++ks) {
            const int k0 = ks * 16;
            uint32_t af[2][4], bf[8][2];
#pragma unroll
            for (int mt = 0; mt < 2; ++mt) {
                int row = warp_m * 32 + mt * 16 + a_rowc;
                uint32_t addr = sA + (row * PADH + k0 + a_kofs) * 2;
                asm volatile(
                    "ldmatrix.sync.aligned.m8n8.x4.shared.b16 {%0,%1,%2,%3}, [%4];"
                    : "=r"(af[mt][0]), "=r"(af[mt][1]), "=r"(af[mt][2]), "=r"(af[mt][3])
                    : "r"(addr));
            }
#pragma unroll
            for (int np = 0; np < 4; ++np) {           // covers nt = 2np, 2np+1
                int row = warp_n * 64 + np * 16 + b_rowc;
                uint32_t addr = sB + (row * PADH + k0 + b_kofs) * 2;
                asm volatile(
                    "ldmatrix.sync.aligned.m8n8.x4.shared.b16 {%0,%1,%2,%3}, [%4];"
                    : "=r"(bf[2 * np][0]), "=r"(bf[2 * np][1]),
                      "=r"(bf[2 * np + 1][0]), "=r"(bf[2 * np + 1][1])
                    : "r"(addr));
            }
#pragma unroll
            for (int mt = 0; mt < 2; ++mt)
#pragma unroll
                for (int nt = 0; nt < 8; ++nt) {
                    asm volatile(
                        "mma.sync.aligned.m16n8k16.row.col.f32.f16.f16.f32 "
                        "{%0,%1,%2,%3}, {%4,%5,%6,%7}, {%8,%9}, {%0,%1,%2,%3};"
                        : "+f"(acc[mt][nt][0]), "+f"(acc[mt][nt][1]),
                          "+f"(acc[mt][nt][2]), "+f"(acc[mt][nt][3])
                        : "r"(af[mt][0]), "r"(af[mt][1]), "r"(af[mt][2]), "r"(af[mt][3]),
                          "r"(bf[nt][0]), "r"(bf[nt][1]));
                }
        }
    }

    const int gid  = lane >> 2;
    const int tidg = lane & 3;
#pragma unroll
    for (int mt = 0; mt < 2; ++mt) {
        const int row0 = bm + warp_m * 32 + mt * 16 + gid;
#pragma unroll
        for (int nt = 0; nt < 8; ++nt) {
            const int col = bn + warp_n * 64 + nt * 8 + tidg * 2;
            float a0 = acc[mt][nt][0] * alpha, a1 = acc[mt][nt][1] * alpha;
            float a2 = acc[mt][nt][2] * alpha, a3 = acc[mt][nt][3] * alpha;
            if constexpr (sizeof(OutT) == 2) {
                __half2 v0 = __floats2half2_rn(a0, a1);
                __half2 v1 = __floats2half2_rn(a2, a3);
                *(__half2*)((__half*)C + (long)row0 * ldc + col)       = v0;
                *(__half2*)((__half*)C + (long)(row0 + 8) * ldc + col) = v1;
            } else {
                float2 v0 = {a0, a1};
                float2 v1 = {a2, a3};
                *(float2*)((float*)C + (long)row0 * ldc + col)       = v0;
                *(float2*)((float*)C + (long)(row0 + 8) * ldc + col) = v1;
            }
        }
    }
}

// Fused Q + KV GEMM: 1024 CTAs of 512 threads.
//   [0, 512)    : Q tiles  (4 N-tiles x 128 M-tiles)
//   [512, 1024) : KV tiles (8 N-tiles x 64 M-tiles)
__global__ __launch_bounds__(NTHREADS, 1)
void qkv_gemm_kernel(const __half* __restrict__ Xh, const __half* __restrict__ WqT,
                     __half* __restrict__ Qh, __half* __restrict__ KVh,
                     const int* __restrict__ qrow, const int* __restrict__ kvrow)
{
    int id = blockIdx.x;
    if (id < 512) {
        gemm_body<__half>(Xh, WqT, Qh, qrow, 1024, id & 3, id >> 2, SCALE);
    } else {
        id -= 512;
        gemm_body<__half>(Xh, WqT + (long)DIM * DIM, KVh, kvrow, 2048,
                          id & 7, id >> 3, 1.0f);
    }
}

// Projection GEMM: 128x256 tiles -> 512 CTAs of 512 threads.
__global__ __launch_bounds__(NTHREADS, 1)
void proj_gemm_kernel(const __half* __restrict__ Oh, const __half* __restrict__ WpT,
                      float* __restrict__ out)
{
    gemm_body<float>(Oh, WpT, out, nullptr, 1024, blockIdx.x & 3, blockIdx.x >> 2, 1.0f);
}

// ---------------- tensor-core fused segment attention ------------------------
#define APAD 72
__global__ __launch_bounds__(128)
void attn_kernel(const int* __restrict__ hmap)
{
    const int s = blockIdx.x, h = blockIdx.y, b = blockIdx.z;
    __shared__ __half Qs[64][APAD];
    __shared__ __half Ks[32][APAD];
    __shared__ __half Vs[32][APAD];

    const int tid  = threadIdx.x;
    const int wid  = tid >> 5;
    const int lane = tid & 31;
    const int gid  = lane >> 2;
    const int tidg = lane & 3;

    const __half* Qbase = g_Qh + ((long)(b * SEQLEN + s * SEG)) * DIM + h * HEAD_DIM;
    for (int l = tid; l < 64 * 8; l += 128) {
        int r = l >> 3, g = l & 7;
        *(float4*)&Qs[r][g * 8] = *(const float4*)(Qbase + (long)r * DIM + g * 8);
    }
    const __half* Kbase = g_KVh + ((long)(b * (SEQLEN / 2) + s * KSEG)) * (2 * DIM) + h * HEAD_DIM;
    const __half* Vbase = Kbase + DIM;
    for (int l = tid; l < 32 * 8; l += 128) {
        int r = l >> 3, g = l & 7;
        *(float4*)&Ks[r][g * 8] = *(const float4*)(Kbase + (long)r * (2 * DIM) + g * 8);
        *(float4*)&Vs[r][g * 8] = *(const float4*)(Vbase + (long)r * (2 * DIM) + g * 8);
    }
    __syncthreads();

    const int a_quad = lane >> 3;
    const int a_rowc = (a_quad & 1) * 8 + (lane & 7);
    const int a_kofs = (a_quad >> 1) * 8;
    const int b_rin  = lane & 7;
    const int b_kofs = ((lane >> 3) & 1) * 8;

    float sacc[4][4];
#pragma unroll
    for (int nt = 0; nt < 4; nt++)
#pragma unroll
        for (int r = 0; r < 4; r++) sacc[nt][r] = 0.0f;

#pragma unroll
    for (int ks = 0; ks < 4; ++ks) {
        const int k0 = ks * 16;
        uint32_t af[4], bf[4][2];
        {
            uint32_t addr = smem_u32(&Qs[wid * 16 + a_rowc][k0 + a_kofs]);
            asm volatile(
                "ldmatrix.sync.aligned.m8n8.x4.shared.b16 {%0,%1,%2,%3}, [%4];"
                : "=r"(af[0]), "=r"(af[1]), "=r"(af[2]), "=r"(af[3]) : "r"(addr));
        }
#pragma unroll
        for (int nt = 0; nt < 4; ++nt) {
            uint32_t addr = smem_u32(&Ks[nt * 8 + b_rin][k0 + b_kofs]);
            asm volatile(
                "ldmatrix.sync.aligned.m8n8.x2.shared.b16 {%0,%1}, [%2];"
                : "=r"(bf[nt][0]), "=r"(bf[nt][1]) : "r"(addr));
        }
#pragma unroll
        for (int nt = 0; nt < 4; ++nt)
            asm volatile(
                "mma.sync.aligned.m16n8k16.row.col.f32.f16.f16.f32 "
                "{%0,%1,%2,%3}, {%4,%5,%6,%7}, {%8,%9}, {%0,%1,%2,%3};"
                : "+f"(sacc[nt][0]), "+f"(sacc[nt][1]),
                  "+f"(sacc[nt][2]), "+f"(sacc[nt][3])
                : "r"(af[0]), "r"(af[1]), "r"(af[2]), "r"(af[3]),
                  "r"(bf[nt][0]), "r"(bf[nt][1]));
    }

    float mx0 = -1e30f, mx1 = -1e30f;
#pragma unroll
    for (int nt = 0; nt < 4; nt++) {
        mx0 = fmaxf(mx0, fmaxf(sacc[nt][0], sacc[nt][1]));
        mx1 = fmaxf(mx1, fmaxf(sacc[nt][2], sacc[nt][3]));
    }
    mx0 = fmaxf(mx0, __shfl_xor_sync(0xffffffffu, mx0, 1));
    mx0 = fmaxf(mx0, __shfl_xor_sync(0xffffffffu, mx0, 2));
    mx1 = fmaxf(mx1, __shfl_xor_sync(0xffffffffu, mx1, 1));
    mx1 = fmaxf(mx1, __shfl_xor_sync(0xffffffffu, mx1, 2));

    float sum0 = 0.0f, sum1 = 0.0f;
#pragma unroll
    for (int nt = 0; nt < 4; nt++) {
        sacc[nt][0] = __expf(sacc[nt][0] - mx0); sum0 += sacc[nt][0];
        sacc[nt][1] = __expf(sacc[nt][1] - mx0); sum0 += sacc[nt][1];
        sacc[nt][2] = __expf(sacc[nt][2] - mx1); sum1 += sacc[nt][2];
        sacc[nt][3] = __expf(sacc[nt][3] - mx1); sum1 += sacc[nt][3];
    }
    sum0 += __shfl_xor_sync(0xffffffffu, sum0, 1);
    sum0 += __shfl_xor_sync(0xffffffffu, sum0, 2);
    sum1 += __shfl_xor_sync(0xffffffffu, sum1, 1);
    sum1 += __shfl_xor_sync(0xffffffffu, sum1, 2);
    const float inv0 = 1.0f / sum0, inv1 = 1.0f / sum1;

    uint32_t pa[2][4];
#pragma unroll
    for (int j = 0; j < 2; j++) {
        __half2 h0 = __floats2half2_rn(sacc[2 * j][0] * inv0, sacc[2 * j][1] * inv0);
        __half2 h1 = __floats2half2_rn(sacc[2 * j][2] * inv1, sacc[2 * j][3] * inv1);
        __half2 h2_ = __floats2half2_rn(sacc[2 * j + 1][0] * inv0, sacc[2 * j + 1][1] * inv0);
        __half2 h3 = __floats2half2_rn(sacc[2 * j + 1][2] * inv1, sacc[2 * j + 1][3] * inv1);
        pa[j][0] = *(uint32_t*)&h0; pa[j][1] = *(uint32_t*)&h1;
        pa[j][2] = *(uint32_t*)&h2_; pa[j][3] = *(uint32_t*)&h3;
    }

    float oacc[8][4];
#pragma unroll
    for (int nt = 0; nt < 8; nt++)
#pragma unroll
        for (int r = 0; r < 4; r++) oacc[nt][r] = 0.0f;

#pragma unroll
    for (int nt = 0; nt < 8; ++nt) {
        uint32_t vb[4];
        uint32_t addr = smem_u32(&Vs[lane][nt * 8]);
        asm volatile(
            "ldmatrix.sync.aligned.m8n8.x4.trans.shared.b16 {%0,%1,%2,%3}, [%4];"
            : "=r"(vb[0]), "=r"(vb[1]), "=r"(vb[2]), "=r"(vb[3]) : "r"(addr));
#pragma unroll
        for (int j = 0; j < 2; ++j)
            asm volatile(
                "mma.sync.aligned.m16n8k16.row.col.f32.f16.f16.f32 "
                "{%0,%1,%2,%3}, {%4,%5,%6,%7}, {%8,%9}, {%0,%1,%2,%3};"
                : "+f"(oacc[nt][0]), "+f"(oacc[nt][1]),
                  "+f"(oacc[nt][2]), "+f"(oacc[nt][3])
                : "r"(pa[j][0]), "r"(pa[j][1]), "r"(pa[j][2]), "r"(pa[j][3]),
                  "r"(vb[2 * j]), "r"(vb[2 * j + 1]));
    }

    const int r0 = wid * 16 + gid;
    const int pos0 = hmap[s * SEG + r0];
    const int pos1 = hmap[s * SEG + r0 + 8];
    __half* Op0 = g_Oh + ((long)(b * SEQLEN + pos0)) * DIM + h * HEAD_DIM;
    __half* Op1 = g_Oh + ((long)(b * SEQLEN + pos1)) * DIM + h * HEAD_DIM;
#pragma unroll
    for (int nt = 0; nt < 8; ++nt) {
        __half2 v0 = __floats2half2_rn(oacc[nt][0], oacc[nt][1]);
        __half2 v1 = __floats2half2_rn(oacc[nt][2], oacc[nt][3]);
        *(__half2*)(Op0 + nt * 8 + tidg * 2) = v0;
        *(__half2*)(Op1 + nt * 8 + tidg * 2) = v1;
    }
}

// ---------------- launch ------------------------------------------------------
extern "C" void kernel_launch(void* const* d_in, const int* in_sizes, int n_in,
                              void* d_out, int out_size)
{
    const float* x      = (const float*)d_in[0];
    const float* w_qkv  = (const float*)d_in[1];
    const float* w_proj = (const float*)d_in[2];
    const int*   hmap   = (const int*)  d_in[3];
    float* out = (float*)d_out;

    __half* Xh;  cudaGetSymbolAddress((void**)&Xh,  g_Xh);
    __half* Qh;  cudaGetSymbolAddress((void**)&Qh,  g_Qh);
    __half* KVh; cudaGetSymbolAddress((void**)&KVh, g_KVh);
    __half* Oh;  cudaGetSymbolAddress((void**)&Oh,  g_Oh);
    __half* WqT; cudaGetSymbolAddress((void**)&WqT, g_WqkvT);
    __half* WpT; cudaGetSymbolAddress((void**)&WpT, g_WprojT);
    int* qrow;  cudaGetSymbolAddress((void**)&qrow,  g_qrow);
    int* kvrow; cudaGetSymbolAddress((void**)&kvrow, g_kvrow);

    static bool attr_done = false;
    if (!attr_done) {
        cudaFuncSetAttribute(qkv_gemm_kernel,
                             cudaFuncAttributeMaxDynamicSharedMemorySize, GSMEM);
        cudaFuncSetAttribute(proj_gemm_kernel,
                             cudaFuncAttributeMaxDynamicSharedMemorySize, GSMEM);
        attr_done = true;
    }

    // 1. fused prep: x->fp16 + weight transposes + gather maps (one launch)
    prep_kernel<<<20544, 256>>>(x, w_qkv, w_proj, hmap);

    // 2+3. fused Q (pre-scaled) and KV GEMMs: 512 + 512 tiles of 128x256
    qkv_gemm_kernel<<<1024, NTHREADS, GSMEM>>>(Xh, WqT, Qh, KVh, qrow, kvrow);

    // 4. tensor-core fused segment attention (+ inverse permutation)
    attn_kernel<<<dim3(NSEG, HEADS, BATCH), 128>>>(hmap);

    // 5. out = O @ w_proj (128x256 tiles, 512 CTAs)
    proj_gemm_kernel<<<512, NTHREADS, GSMEM>>>(Oh, WpT, out);
}

// round 16
// speedup vs baseline: 1.2107x; 1.2107x over previous
#include <cuda_runtime.h>
#include <cuda_fp16.h>
#include <cstdint>
#include <math.h>

#define BATCH    4
#define SEQLEN   4096
#define DIM      1024
#define HEADS    16
#define HEAD_DIM 64
#define SEG      64
#define NSEG     (SEQLEN / SEG)     // 64
#define KSEG     (SEG / 2)          // 32 (dilation 2)
#define KDIM     1024               // GEMM reduction dim
#define SCALE    0.125f             // 64^-0.5

// ---------------- scratch (static device globals; no allocs allowed) --------
__device__ __half g_Xh [BATCH * SEQLEN * DIM];               // fp16 x
__device__ __half g_Qh [BATCH * SEQLEN * DIM];               // hilbert-ordered, pre-scaled Q
__device__ __half g_KVh[BATCH * (SEQLEN / 2) * (2 * DIM)];   // dilated K|V (fp16)
__device__ __half g_Oh [BATCH * SEQLEN * DIM];               // attn out, original order
__device__ __half g_WqkvT[3 * DIM * DIM];                    // w_qkv^T fp16
__device__ __half g_WprojT[DIM * DIM];                       // w_proj^T fp16
__device__ int    g_qrow [BATCH * SEQLEN];
__device__ int    g_kvrow[BATCH * (SEQLEN / 2)];

// ---------------- helpers -----------------------------------------------------
__device__ __forceinline__ uint32_t smem_u32(const void* p) {
    uint32_t a;
    asm("{ .reg .u64 t; cvta.to.shared.u64 t, %1; cvt.u32.u64 %0, t; }" : "=r"(a) : "l"(p));
    return a;
}
__device__ __forceinline__ void cp_async16(uint32_t dst, const void* src) {
    asm volatile("cp.async.ca.shared.global [%0], [%1], 16;" :: "r"(dst), "l"(src));
}
__device__ __forceinline__ void cp_commit() {
    asm volatile("cp.async.commit_group;" ::: "memory");
}
template <int N>
__device__ __forceinline__ void cp_wait() {
    asm volatile("cp.async.wait_group %0;" :: "n"(N) : "memory");
}

// ---------------- fused prep: x->fp16, transposes, gather maps ---------------
__device__ __forceinline__ void transpose_body(const float* __restrict__ W,
                                               __half* __restrict__ Wt,
                                               int rows, int cols, int bxi, int byi,
                                               int tx, int ty)
{
    __shared__ float t[32][33];
    int bx = bxi * 32, by = byi * 32;
#pragma unroll
    for (int i = 0; i < 32; i += 8) {
        int y = by + ty + i, x = bx + tx;
        t[ty + i][tx] = W[(long)y * cols + x];
    }
    __syncthreads();
#pragma unroll
    for (int i = 0; i < 32; i += 8) {
        int y = bx + ty + i, x = by + tx;
        Wt[(long)y * rows + x] = __float2half_rn(t[tx][ty + i]);
    }
}

__global__ __launch_bounds__(256)
void prep_kernel(const float* __restrict__ x,
                 const float* __restrict__ w_qkv, const float* __restrict__ w_proj,
                 const int* __restrict__ hmap)
{
    const int id = blockIdx.x;
    if (id < 16384) {
        long t = (long)id * 256 + threadIdx.x;
        float4 v = ((const float4*)x)[t];
        __half2* dst = (__half2*)g_Xh + t * 2;
        dst[0] = __floats2half2_rn(v.x, v.y);
        dst[1] = __floats2half2_rn(v.z, v.w);
        return;
    }
    const int tx = threadIdx.x & 31, ty = threadIdx.x >> 5;
    if (id < 19456) {
        int i2 = id - 16384;
        transpose_body(w_qkv, g_WqkvT, DIM, 3 * DIM, i2 % 96, i2 / 96, tx, ty);
    } else if (id < 20480) {
        int i2 = id - 19456;
        transpose_body(w_proj, g_WprojT, DIM, DIM, i2 % 32, i2 / 32, tx, ty);
    } else {
        int t = (id - 20480) * 256 + threadIdx.x;
        if (t < BATCH * SEQLEN) {
            int b = t / SEQLEN, i = t % SEQLEN;
            g_qrow[t] = b * SEQLEN + hmap[i];
        }
        if (t < BATCH * (SEQLEN / 2)) {
            int b = t / (SEQLEN / 2), m = t % (SEQLEN / 2);
            int s = m / KSEG, j = m % KSEG;
            g_kvrow[t] = b * SEQLEN + hmap[s * SEG + 2 * j];
        }
    }
}

// ---------------- fp16 mma GEMM body -------------------------------------------
// CTA tile 128x128, 8 warps in 2(M)x4(N), warp tile 64x32. 2 CTAs/SM (R13 shape).
// K-chunk 64 (16 chunks): half the syncs of R13, same crossbar bytes.
// Row stride 72 halves (144B): granule (9*row+g) mod 8 distinct over 8 rows.
#define PADH        72
#define STAGE_H     (128 * PADH)              // halves per operand
#define STAGE_BYTES (2 * STAGE_H * 2)         // A + B = 36864 B
#define NSTAGE      3
#define GSMEM       (NSTAGE * STAGE_BYTES)    // 110592 B/CTA, 2 CTAs = 221184
#define NCHUNK      (KDIM / 64)               // 16

extern __shared__ __align__(16) char dynsmem[];

template <typename OutT>
__device__ __forceinline__ void gemm_body(const __half* __restrict__ A,
                                          const __half* __restrict__ Bt,
                                          OutT* __restrict__ C,
                                          const int* __restrict__ rowidx,
                                          int ldc, int bx, int by, float alpha)
{
    __shared__ int rowid[128];

    const int tid   = threadIdx.x;
    const int wid   = tid >> 5;
    const int lane  = tid & 31;
    const int warp_m = wid >> 2;      // 0..1
    const int warp_n = wid & 3;       // 0..3
    const int bm = by * 128;
    const int bn = bx * 128;

    if (tid < 128) rowid[tid] = rowidx ? rowidx[bm + tid] : (bm + tid);
    __syncthreads();

    const uint32_t smb = smem_u32(dynsmem);

    auto issue = [&](int chunk) {
        const int s = chunk % NSTAGE;
        const int koff = chunk * 64;
        const uint32_t sA = smb + s * STAGE_BYTES;
        const uint32_t sB = sA + STAGE_H * 2;
#pragma unroll
        for (int i = 0; i < 4; i++) {                 // A: 128 rows x 8 granules
            int idx = tid + i * 256;
            int row = idx >> 3, g = idx & 7;
            cp_async16(sA + row * (PADH * 2) + g * 16,
                       A + (long)rowid[row] * KDIM + koff + g * 8);
        }
#pragma unroll
        for (int i = 0; i < 4; i++) {                 // B: 128 rows x 8 granules
            int idx = tid + i * 256;
            int row = idx >> 3, g = idx & 7;
            cp_async16(sB + row * (PADH * 2) + g * 16,
                       Bt + (long)(bn + row) * KDIM + koff + g * 8);
        }
        cp_commit();
    };

    float acc[4][4][4];
#pragma unroll
    for (int i = 0; i < 4; i++)
#pragma unroll
        for (int j = 0; j < 4; j++)
#pragma unroll
            for (int r = 0; r < 4; r++) acc[i][j][r] = 0.0f;

    const int a_quad = lane >> 3;
    const int a_rowc = (a_quad & 1) * 8 + (lane & 7);
    const int a_kofs = (a_quad >> 1) * 8;
    const int b_rowc = ((lane >> 4) & 1) * 8 + (lane & 7);
    const int b_kofs = ((lane >> 3) & 1) * 8;

    issue(0); issue(1);

    for (int c = 0; c < NCHUNK; ++c) {
        if (c == NCHUNK - 1) cp_wait<0>();
        else                 cp_wait<1>();
        __syncthreads();
        if (c + 2 < NCHUNK) issue(c + 2);

        const uint32_t sA = smb + (c % NSTAGE) * STAGE_BYTES;
        const uint32_t sB = sA + STAGE_H * 2;

#pragma unroll
        for (int ks = 0; ks < 4; ++ks) {              // 4 k16 per 64-chunk
            const int k0 = ks * 16;
            uint32_t af[4][4], bf[4][2];
#pragma unroll
            for (int mt = 0; mt < 4; ++mt) {
                int row = warp_m * 64 + mt * 16 + a_rowc;
                uint32_t addr = sA + (row * PADH + k0 + a_kofs) * 2;
                asm volatile(
                    "ldmatrix.sync.aligned.m8n8.x4.shared.b16 {%0,%1,%2,%3}, [%4];"
                    : "=r"(af[mt][0]), "=r"(af[mt][1]), "=r"(af[mt][2]), "=r"(af[mt][3])
                    : "r"(addr));
            }
#pragma unroll
            for (int np = 0; np < 2; ++np) {
                int row = warp_n * 32 + np * 16 + b_rowc;
                uint32_t addr = sB + (row * PADH + k0 + b_kofs) * 2;
                asm volatile(
                    "ldmatrix.sync.aligned.m8n8.x4.shared.b16 {%0,%1,%2,%3}, [%4];"
                    : "=r"(bf[2 * np][0]), "=r"(bf[2 * np][1]),
                      "=r"(bf[2 * np + 1][0]), "=r"(bf[2 * np + 1][1])
                    : "r"(addr));
            }
#pragma unroll
            for (int mt = 0; mt < 4; ++mt)
#pragma unroll
                for (int nt = 0; nt < 4; ++nt) {
                    asm volatile(
                        "mma.sync.aligned.m16n8k16.row.col.f32.f16.f16.f32 "
                        "{%0,%1,%2,%3}, {%4,%5,%6,%7}, {%8,%9}, {%0,%1,%2,%3};"
                        : "+f"(acc[mt][nt][0]), "+f"(acc[mt][nt][1]),
                          "+f"(acc[mt][nt][2]), "+f"(acc[mt][nt][3])
                        : "r"(af[mt][0]), "r"(af[mt][1]), "r"(af[mt][2]), "r"(af[mt][3]),
                          "r"(bf[nt][0]), "r"(bf[nt][1]));
                }
        }
    }

    const int gid  = lane >> 2;
    const int tidg = lane & 3;
#pragma unroll
    for (int mt = 0; mt < 4; ++mt) {
        const int row0 = bm + warp_m * 64 + mt * 16 + gid;
#pragma unroll
        for (int nt = 0; nt < 4; ++nt) {
            const int col = bn + warp_n * 32 + nt * 8 + tidg * 2;
            float a0 = acc[mt][nt][0] * alpha, a1 = acc[mt][nt][1] * alpha;
            float a2 = acc[mt][nt][2] * alpha, a3 = acc[mt][nt][3] * alpha;
            if constexpr (sizeof(OutT) == 2) {
                __half2 v0 = __floats2half2_rn(a0, a1);
                __half2 v1 = __floats2half2_rn(a2, a3);
                *(__half2*)((__half*)C + (long)row0 * ldc + col)       = v0;
                *(__half2*)((__half*)C + (long)(row0 + 8) * ldc + col) = v1;
            } else {
                float2 v0 = {a0, a1};
                float2 v1 = {a2, a3};
                *(float2*)((float*)C + (long)row0 * ldc + col)       = v0;
                *(float2*)((float*)C + (long)(row0 + 8) * ldc + col) = v1;
            }
        }
    }
}

// Fused Q + KV GEMM: 2048 CTAs (1024 Q + 1024 KV), 128x128 tiles.
__global__ __launch_bounds__(256, 2)
void qkv_gemm_kernel(const __half* __restrict__ Xh, const __half* __restrict__ WqT,
                     __half* __restrict__ Qh, __half* __restrict__ KVh,
                     const int* __restrict__ qrow, const int* __restrict__ kvrow)
{
    int id = blockIdx.x;
    if (id < 1024) {
        gemm_body<__half>(Xh, WqT, Qh, qrow, 1024, id & 7, id >> 3, SCALE);
    } else {
        id -= 1024;
        gemm_body<__half>(Xh, WqT + (long)DIM * DIM, KVh, kvrow, 2048, id & 15, id >> 4, 1.0f);
    }
}

// Projection GEMM: 128x128 tiles, 1024 CTAs.
__global__ __launch_bounds__(256, 2)
void proj_gemm_kernel(const __half* __restrict__ Oh, const __half* __restrict__ WpT,
                      float* __restrict__ out)
{
    gemm_body<float>(Oh, WpT, out, nullptr, 1024, blockIdx.x & 7, blockIdx.x >> 3, 1.0f);
}

// ---------------- tensor-core fused segment attention ------------------------
#define APAD 72
__global__ __launch_bounds__(128)
void attn_kernel(const int* __restrict__ hmap)
{
    const int s = blockIdx.x, h = blockIdx.y, b = blockIdx.z;
    __shared__ __half Qs[64][APAD];
    __shared__ __half Ks[32][APAD];
    __shared__ __half Vs[32][APAD];

    const int tid  = threadIdx.x;
    const int wid  = tid >> 5;
    const int lane = tid & 31;
    const int gid  = lane >> 2;
    const int tidg = lane & 3;

    const __half* Qbase = g_Qh + ((long)(b * SEQLEN + s * SEG)) * DIM + h * HEAD_DIM;
    for (int l = tid; l < 64 * 8; l += 128) {
        int r = l >> 3, g = l & 7;
        *(float4*)&Qs[r][g * 8] = *(const float4*)(Qbase + (long)r * DIM + g * 8);
    }
    const __half* Kbase = g_KVh + ((long)(b * (SEQLEN / 2) + s * KSEG)) * (2 * DIM) + h * HEAD_DIM;
    const __half* Vbase = Kbase + DIM;
    for (int l = tid; l < 32 * 8; l += 128) {
        int r = l >> 3, g = l & 7;
        *(float4*)&Ks[r][g * 8] = *(const float4*)(Kbase + (long)r * (2 * DIM) + g * 8);
        *(float4*)&Vs[r][g * 8] = *(const float4*)(Vbase + (long)r * (2 * DIM) + g * 8);
    }
    __syncthreads();

    const int a_quad = lane >> 3;
    const int a_rowc = (a_quad & 1) * 8 + (lane & 7);
    const int a_kofs = (a_quad >> 1) * 8;
    const int b_rin  = lane & 7;
    const int b_kofs = ((lane >> 3) & 1) * 8;

    float sacc[4][4];
#pragma unroll
    for (int nt = 0; nt < 4; nt++)
#pragma unroll
        for (int r = 0; r < 4; r++) sacc[nt][r] = 0.0f;

#pragma unroll
    for (int ks = 0; ks < 4; ++ks) {
        const int k0 = ks * 16;
        uint32_t af[4], bf[4][2];
        {
            uint32_t addr = smem_u32(&Qs[wid * 16 + a_rowc][k0 + a_kofs]);
            asm volatile(
                "ldmatrix.sync.aligned.m8n8.x4.shared.b16 {%0,%1,%2,%3}, [%4];"
                : "=r"(af[0]), "=r"(af[1]), "=r"(af[2]), "=r"(af[3]) : "r"(addr));
        }
#pragma unroll
        for (int nt = 0; nt < 4; ++nt) {
            uint32_t addr = smem_u32(&Ks[nt * 8 + b_rin][k0 + b_kofs]);
            asm volatile(
                "ldmatrix.sync.aligned.m8n8.x2.shared.b16 {%0,%1}, [%2];"
                : "=r"(bf[nt][0]), "=r"(bf[nt][1]) : "r"(addr));
        }
#pragma unroll
        for (int nt = 0; nt < 4; ++nt)
            asm volatile(
                "mma.sync.aligned.m16n8k16.row.col.f32.f16.f16.f32 "
                "{%0,%1,%2,%3}, {%4,%5,%6,%7}, {%8,%9}, {%0,%1,%2,%3};"
                : "+f"(sacc[nt][0]), "+f"(sacc[nt][1]),
                  "+f"(sacc[nt][2]), "+f"(sacc[nt][3])
                : "r"(af[0]), "r"(af[1]), "r"(af[2]), "r"(af[3]),
                  "r"(bf[nt][0]), "r"(bf[nt][1]));
    }

    float mx0 = -1e30f, mx1 = -1e30f;
#pragma unroll
    for (int nt = 0; nt < 4; nt++) {
        mx0 = fmaxf(mx0, fmaxf(sacc[nt][0], sacc[nt][1]));
        mx1 = fmaxf(mx1, fmaxf(sacc[nt][2], sacc[nt][3]));
    }
    mx0 = fmaxf(mx0, __shfl_xor_sync(0xffffffffu, mx0, 1));
    mx0 = fmaxf(mx0, __shfl_xor_sync(0xffffffffu, mx0, 2));
    mx1 = fmaxf(mx1, __shfl_xor_sync(0xffffffffu, mx1, 1));
    mx1 = fmaxf(mx1, __shfl_xor_sync(0xffffffffu, mx1, 2));

    float sum0 = 0.0f, sum1 = 0.0f;
#pragma unroll
    for (int nt = 0; nt < 4; nt++) {
        sacc[nt][0] = __expf(sacc[nt][0] - mx0); sum0 += sacc[nt][0];
        sacc[nt][1] = __expf(sacc[nt][1] - mx0); sum0 += sacc[nt][1];
        sacc[nt][2] = __expf(sacc[nt][2] - mx1); sum1 += sacc[nt][2];
        sacc[nt][3] = __expf(sacc[nt][3] - mx1); sum1 += sacc[nt][3];
    }
    sum0 += __shfl_xor_sync(0xffffffffu, sum0, 1);
    sum0 += __shfl_xor_sync(0xffffffffu, sum0, 2);
    sum1 += __shfl_xor_sync(0xffffffffu, sum1, 1);
    sum1 += __shfl_xor_sync(0xffffffffu, sum1, 2);
    const float inv0 = 1.0f / sum0, inv1 = 1.0f / sum1;

    uint32_t pa[2][4];
#pragma unroll
    for (int j = 0; j < 2; j++) {
        __half2 h0 = __floats2half2_rn(sacc[2 * j][0] * inv0, sacc[2 * j][1] * inv0);
        __half2 h1 = __floats2half2_rn(sacc[2 * j][2] * inv1, sacc[2 * j][3] * inv1);
        __half2 h2_ = __floats2half2_rn(sacc[2 * j + 1][0] * inv0, sacc[2 * j + 1][1] * inv0);
        __half2 h3 = __floats2half2_rn(sacc[2 * j + 1][2] * inv1, sacc[2 * j + 1][3] * inv1);
        pa[j][0] = *(uint32_t*)&h0; pa[j][1] = *(uint32_t*)&h1;
        pa[j][2] = *(uint32_t*)&h2_; pa[j][3] = *(uint32_t*)&h3;
    }

    float oacc[8][4];
#pragma unroll
    for (int nt = 0; nt < 8; nt++)
#pragma unroll
        for (int r = 0; r < 4; r++) oacc[nt][r] = 0.0f;

#pragma unroll
    for (int nt = 0; nt < 8; ++nt) {
        uint32_t vb[4];
        uint32_t addr = smem_u32(&Vs[lane][nt * 8]);
        asm volatile(
            "ldmatrix.sync.aligned.m8n8.x4.trans.shared.b16 {%0,%1,%2,%3}, [%4];"
            : "=r"(vb[0]), "=r"(vb[1]), "=r"(vb[2]), "=r"(vb[3]) : "r"(addr));
#pragma unroll
        for (int j = 0; j < 2; ++j)
            asm volatile(
                "mma.sync.aligned.m16n8k16.row.col.f32.f16.f16.f32 "
                "{%0,%1,%2,%3}, {%4,%5,%6,%7}, {%8,%9}, {%0,%1,%2,%3};"
                : "+f"(oacc[nt][0]), "+f"(oacc[nt][1]),
                  "+f"(oacc[nt][2]), "+f"(oacc[nt][3])
                : "r"(pa[j][0]), "r"(pa[j][1]), "r"(pa[j][2]), "r"(pa[j][3]),
                  "r"(vb[2 * j]), "r"(vb[2 * j + 1]));
    }

    const int r0 = wid * 16 + gid;
    const int pos0 = hmap[s * SEG + r0];
    const int pos1 = hmap[s * SEG + r0 + 8];
    __half* Op0 = g_Oh + ((long)(b * SEQLEN + pos0)) * DIM + h * HEAD_DIM;
    __half* Op1 = g_Oh + ((long)(b * SEQLEN + pos1)) * DIM + h * HEAD_DIM;
#pragma unroll
    for (int nt = 0; nt < 8; ++nt) {
        __half2 v0 = __floats2half2_rn(oacc[nt][0], oacc[nt][1]);
        __half2 v1 = __floats2half2_rn(oacc[nt][2], oacc[nt][3]);
        *(__half2*)(Op0 + nt * 8 + tidg * 2) = v0;
        *(__half2*)(Op1 + nt * 8 + tidg * 2) = v1;
    }
}

// ---------------- launch ------------------------------------------------------
extern "C" void kernel_launch(void* const* d_in, const int* in_sizes, int n_in,
                              void* d_out, int out_size)
{
    const float* x      = (const float*)d_in[0];
    const float* w_qkv  = (const float*)d_in[1];
    const float* w_proj = (const float*)d_in[2];
    const int*   hmap   = (const int*)  d_in[3];
    float* out = (float*)d_out;

    __half* Xh;  cudaGetSymbolAddress((void**)&Xh,  g_Xh);
    __half* Qh;  cudaGetSymbolAddress((void**)&Qh,  g_Qh);
    __half* KVh; cudaGetSymbolAddress((void**)&KVh, g_KVh);
    __half* Oh;  cudaGetSymbolAddress((void**)&Oh,  g_Oh);
    __half* WqT; cudaGetSymbolAddress((void**)&WqT, g_WqkvT);
    __half* WpT; cudaGetSymbolAddress((void**)&WpT, g_WprojT);
    int* qrow;  cudaGetSymbolAddress((void**)&qrow,  g_qrow);
    int* kvrow; cudaGetSymbolAddress((void**)&kvrow, g_kvrow);

    static bool attr_done = false;
    if (!attr_done) {
        cudaFuncSetAttribute(qkv_gemm_kernel,
                             cudaFuncAttributeMaxDynamicSharedMemorySize, GSMEM);
        cudaFuncSetAttribute(proj_gemm_kernel,
                             cudaFuncAttributeMaxDynamicSharedMemorySize, GSMEM);
        attr_done = true;
    }

    // 1. fused prep: x->fp16 + weight transposes + gather maps (one launch)
    prep_kernel<<<20544, 256>>>(x, w_qkv, w_proj, hmap);

    // 2+3. fused Q (pre-scaled) and KV GEMMs
    qkv_gemm_kernel<<<2048, 256, GSMEM>>>(Xh, WqT, Qh, KVh, qrow, kvrow);

    // 4. tensor-core fused segment attention (+ inverse permutation)
    attn_kernel<<<dim3(NSEG, HEADS, BATCH), 128>>>(hmap);

    // 5. out = O @ w_proj (128x128 tiles, 1024 CTAs)
    proj_gemm_kernel<<<1024, 256, GSMEM>>>(Oh, WpT, out);
}

// round 17
// speedup vs baseline: 1.3211x; 1.0912x over previous
#include <cuda_runtime.h>
#include <cuda_fp16.h>
#include <cstdint>
#include <math.h>

#define BATCH    4
#define SEQLEN   4096
#define DIM      1024
#define HEADS    16
#define HEAD_DIM 64
#define SEG      64
#define NSEG     (SEQLEN / SEG)     // 64
#define KSEG     (SEG / 2)          // 32 (dilation 2)
#define KDIM     1024               // GEMM reduction dim
#define SCALE    0.125f             // 64^-0.5

// ---------------- scratch (static device globals; no allocs allowed) --------
__device__ __half g_Xh [BATCH * SEQLEN * DIM];               // fp16 x
__device__ __half g_Qh [BATCH * SEQLEN * DIM];               // hilbert-ordered, pre-scaled Q
__device__ __half g_KVh[BATCH * (SEQLEN / 2) * (2 * DIM)];   // dilated K|V (fp16)
__device__ __half g_Oh [BATCH * SEQLEN * DIM];               // attn out, original order
__device__ __half g_WqkvT[3 * DIM * DIM];                    // w_qkv^T fp16
__device__ __half g_WprojT[DIM * DIM];                       // w_proj^T fp16
__device__ int    g_qrow [BATCH * SEQLEN];
__device__ int    g_kvrow[BATCH * (SEQLEN / 2)];

// ---------------- helpers -----------------------------------------------------
__device__ __forceinline__ uint32_t smem_u32(const void* p) {
    uint32_t a;
    asm("{ .reg .u64 t; cvta.to.shared.u64 t, %1; cvt.u32.u64 %0, t; }" : "=r"(a) : "l"(p));
    return a;
}
__device__ __forceinline__ void cp_async16_cg(uint32_t dst, const void* src) {
    asm volatile("cp.async.cg.shared.global [%0], [%1], 16;" :: "r"(dst), "l"(src));
}
__device__ __forceinline__ void cp_commit() {
    asm volatile("cp.async.commit_group;" ::: "memory");
}
template <int N>
__device__ __forceinline__ void cp_wait() {
    asm volatile("cp.async.wait_group %0;" :: "n"(N) : "memory");
}

// ---------------- fused prep: x->fp16, transposes, gather maps ---------------
__device__ __forceinline__ void transpose_body(const float* __restrict__ W,
                                               __half* __restrict__ Wt,
                                               int rows, int cols, int bxi, int byi,
                                               int tx, int ty)
{
    __shared__ float t[32][33];
    int bx = bxi * 32, by = byi * 32;
#pragma unroll
    for (int i = 0; i < 32; i += 8) {
        int y = by + ty + i, x = bx + tx;
        t[ty + i][tx] = W[(long)y * cols + x];
    }
    __syncthreads();
#pragma unroll
    for (int i = 0; i < 32; i += 8) {
        int y = bx + ty + i, x = by + tx;
        Wt[(long)y * rows + x] = __float2half_rn(t[tx][ty + i]);
    }
}

__global__ __launch_bounds__(256)
void prep_kernel(const float* __restrict__ x,
                 const float* __restrict__ w_qkv, const float* __restrict__ w_proj,
                 const int* __restrict__ hmap)
{
    const int id = blockIdx.x;
    if (id < 16384) {
        long t = (long)id * 256 + threadIdx.x;
        float4 v = ((const float4*)x)[t];
        __half2* dst = (__half2*)g_Xh + t * 2;
        dst[0] = __floats2half2_rn(v.x, v.y);
        dst[1] = __floats2half2_rn(v.z, v.w);
        return;
    }
    const int tx = threadIdx.x & 31, ty = threadIdx.x >> 5;
    if (id < 19456) {
        int i2 = id - 16384;
        transpose_body(w_qkv, g_WqkvT, DIM, 3 * DIM, i2 % 96, i2 / 96, tx, ty);
    } else if (id < 20480) {
        int i2 = id - 19456;
        transpose_body(w_proj, g_WprojT, DIM, DIM, i2 % 32, i2 / 32, tx, ty);
    } else {
        int t = (id - 20480) * 256 + threadIdx.x;
        if (t < BATCH * SEQLEN) {
            int b = t / SEQLEN, i = t % SEQLEN;
            g_qrow[t] = b * SEQLEN + hmap[i];
        }
        if (t < BATCH * (SEQLEN / 2)) {
            int b = t / (SEQLEN / 2), m = t % (SEQLEN / 2);
            int s = m / KSEG, j = m % KSEG;
            g_kvrow[t] = b * SEQLEN + hmap[s * SEG + 2 * j];
        }
    }
}

// ---------------- fp16 mma GEMM body -------------------------------------------
// CTA tile 128x128, 8 warps in 2(M)x4(N), warp tile 64x32. 2 CTAs/SM.
// K-chunk 64 (16 chunks), 3-stage cp.async ring. Row stride 72 halves (144B):
// granule (9*row+g) mod 8 distinct over 8 rows -> conflict-free ldmatrix.
#define PADH        72
#define STAGE_H     (128 * PADH)              // halves per operand
#define STAGE_BYTES (2 * STAGE_H * 2)         // A + B = 36864 B
#define NSTAGE      3
#define GSMEM       (NSTAGE * STAGE_BYTES)    // 110592 B/CTA, 2 CTAs = 221184
#define NCHUNK      (KDIM / 64)               // 16

extern __shared__ __align__(16) char dynsmem[];

template <typename OutT>
__device__ __forceinline__ void gemm_body(const __half* __restrict__ A,
                                          const __half* __restrict__ Bt,
                                          OutT* __restrict__ C,
                                          const int* __restrict__ rowidx,
                                          int ldc, int bx, int by, float alpha)
{
    __shared__ int rowid[128];

    const int tid   = threadIdx.x;
    const int wid   = tid >> 5;
    const int lane  = tid & 31;
    const int warp_m = wid >> 2;      // 0..1
    const int warp_n = wid & 3;       // 0..3
    const int bm = by * 128;
    const int bn = bx * 128;

    if (tid < 128) rowid[tid] = rowidx ? rowidx[bm + tid] : (bm + tid);
    __syncthreads();

    const uint32_t smb = smem_u32(dynsmem);

    auto issue = [&](int chunk) {
        const int s = chunk % NSTAGE;
        const int koff = chunk * 64;
        const uint32_t sA = smb + s * STAGE_BYTES;
        const uint32_t sB = sA + STAGE_H * 2;
#pragma unroll
        for (int i = 0; i < 4; i++) {                 // A: 128 rows x 8 granules
            int idx = tid + i * 256;
            int row = idx >> 3, g = idx & 7;
            cp_async16_cg(sA + row * (PADH * 2) + g * 16,
                          A + (long)rowid[row] * KDIM + koff + g * 8);
        }
#pragma unroll
        for (int i = 0; i < 4; i++) {                 // B: 128 rows x 8 granules
            int idx = tid + i * 256;
            int row = idx >> 3, g = idx & 7;
            cp_async16_cg(sB + row * (PADH * 2) + g * 16,
                          Bt + (long)(bn + row) * KDIM + koff + g * 8);
        }
        cp_commit();
    };

    float acc[4][4][4];
#pragma unroll
    for (int i = 0; i < 4; i++)
#pragma unroll
        for (int j = 0; j < 4; j++)
#pragma unroll
            for (int r = 0; r < 4; r++) acc[i][j][r] = 0.0f;

    const int a_quad = lane >> 3;
    const int a_rowc = (a_quad & 1) * 8 + (lane & 7);
    const int a_kofs = (a_quad >> 1) * 8;
    const int b_rowc = ((lane >> 4) & 1) * 8 + (lane & 7);
    const int b_kofs = ((lane >> 3) & 1) * 8;

    issue(0); issue(1);

    for (int c = 0; c < NCHUNK; ++c) {
        if (c == NCHUNK - 1) cp_wait<0>();
        else                 cp_wait<1>();
        __syncthreads();
        if (c + 2 < NCHUNK) issue(c + 2);

        const uint32_t sA = smb + (c % NSTAGE) * STAGE_BYTES;
        const uint32_t sB = sA + STAGE_H * 2;

#pragma unroll
        for (int ks = 0; ks < 4; ++ks) {              // 4 k16 per 64-chunk
            const int k0 = ks * 16;
            uint32_t af[4][4], bf[4][2];
#pragma unroll
            for (int mt = 0; mt < 4; ++mt) {
                int row = warp_m * 64 + mt * 16 + a_rowc;
                uint32_t addr = sA + (row * PADH + k0 + a_kofs) * 2;
                asm volatile(
                    "ldmatrix.sync.aligned.m8n8.x4.shared.b16 {%0,%1,%2,%3}, [%4];"
                    : "=r"(af[mt][0]), "=r"(af[mt][1]), "=r"(af[mt][2]), "=r"(af[mt][3])
                    : "r"(addr));
            }
#pragma unroll
            for (int np = 0; np < 2; ++np) {
                int row = warp_n * 32 + np * 16 + b_rowc;
                uint32_t addr = sB + (row * PADH + k0 + b_kofs) * 2;
                asm volatile(
                    "ldmatrix.sync.aligned.m8n8.x4.shared.b16 {%0,%1,%2,%3}, [%4];"
                    : "=r"(bf[2 * np][0]), "=r"(bf[2 * np][1]),
                      "=r"(bf[2 * np + 1][0]), "=r"(bf[2 * np + 1][1])
                    : "r"(addr));
            }
#pragma unroll
            for (int mt = 0; mt < 4; ++mt)
#pragma unroll
                for (int nt = 0; nt < 4; ++nt) {
                    asm volatile(
                        "mma.sync.aligned.m16n8k16.row.col.f32.f16.f16.f32 "
                        "{%0,%1,%2,%3}, {%4,%5,%6,%7}, {%8,%9}, {%0,%1,%2,%3};"
                        : "+f"(acc[mt][nt][0]), "+f"(acc[mt][nt][1]),
                          "+f"(acc[mt][nt][2]), "+f"(acc[mt][nt][3])
                        : "r"(af[mt][0]), "r"(af[mt][1]), "r"(af[mt][2]), "r"(af[mt][3]),
                          "r"(bf[nt][0]), "r"(bf[nt][1]));
                }
        }
    }

    const int gid  = lane >> 2;
    const int tidg = lane & 3;
#pragma unroll
    for (int mt = 0; mt < 4; ++mt) {
        const int row0 = bm + warp_m * 64 + mt * 16 + gid;
#pragma unroll
        for (int nt = 0; nt < 4; ++nt) {
            const int col = bn + warp_n * 32 + nt * 8 + tidg * 2;
            float a0 = acc[mt][nt][0] * alpha, a1 = acc[mt][nt][1] * alpha;
            float a2 = acc[mt][nt][2] * alpha, a3 = acc[mt][nt][3] * alpha;
            if constexpr (sizeof(OutT) == 2) {
                __half2 v0 = __floats2half2_rn(a0, a1);
                __half2 v1 = __floats2half2_rn(a2, a3);
                *(__half2*)((__half*)C + (long)row0 * ldc + col)       = v0;
                *(__half2*)((__half*)C + (long)(row0 + 8) * ldc + col) = v1;
            } else {
                float2 v0 = {a0, a1};
                float2 v1 = {a2, a3};
                *(float2*)((float*)C + (long)row0 * ldc + col)       = v0;
                *(float2*)((float*)C + (long)(row0 + 8) * ldc + col) = v1;
            }
        }
    }
}

// Fused Q + KV GEMM: 2048 CTAs (1024 Q + 1024 KV), 128x128 tiles.
__global__ __launch_bounds__(256, 2)
void qkv_gemm_kernel(const __half* __restrict__ Xh, const __half* __restrict__ WqT,
                     __half* __restrict__ Qh, __half* __restrict__ KVh,
                     const int* __restrict__ qrow, const int* __restrict__ kvrow)
{
    int id = blockIdx.x;
    if (id < 1024) {
        gemm_body<__half>(Xh, WqT, Qh, qrow, 1024, id & 7, id >> 3, SCALE);
    } else {
        id -= 1024;
        gemm_body<__half>(Xh, WqT + (long)DIM * DIM, KVh, kvrow, 2048, id & 15, id >> 4, 1.0f);
    }
}

// Projection GEMM: 128x128 tiles, 1024 CTAs.
__global__ __launch_bounds__(256, 2)
void proj_gemm_kernel(const __half* __restrict__ Oh, const __half* __restrict__ WpT,
                      float* __restrict__ out)
{
    gemm_body<float>(Oh, WpT, out, nullptr, 1024, blockIdx.x & 7, blockIdx.x >> 3, 1.0f);
}

// ---------------- tensor-core fused segment attention ------------------------
// 256 threads; warps 0-3 handle segment 2*bx, warps 4-7 handle 2*bx+1.
#define APAD 72
__global__ __launch_bounds__(256)
void attn_kernel(const int* __restrict__ hmap)
{
    const int h = blockIdx.y, b = blockIdx.z;
    __shared__ __half Qs[2][64][APAD];
    __shared__ __half Ks[2][32][APAD];
    __shared__ __half Vs[2][32][APAD];

    const int tid  = threadIdx.x;
    const int wid  = tid >> 5;
    const int sg   = wid >> 2;                 // segment slot 0/1
    const int wloc = wid & 3;                  // warp within segment
    const int s    = blockIdx.x * 2 + sg;
    const int lane = tid & 31;
    const int gid  = lane >> 2;
    const int tidg = lane & 3;
    const int tl   = tid & 127;                // thread within segment group

    // ---- load tiles (16B granules), each 128-thread group loads its segment ----
    const __half* Qbase = g_Qh + ((long)(b * SEQLEN + s * SEG)) * DIM + h * HEAD_DIM;
    for (int l = tl; l < 64 * 8; l += 128) {
        int r = l >> 3, g = l & 7;
        *(float4*)&Qs[sg][r][g * 8] = *(const float4*)(Qbase + (long)r * DIM + g * 8);
    }
    const __half* Kbase = g_KVh + ((long)(b * (SEQLEN / 2) + s * KSEG)) * (2 * DIM) + h * HEAD_DIM;
    const __half* Vbase = Kbase + DIM;
    for (int l = tl; l < 32 * 8; l += 128) {
        int r = l >> 3, g = l & 7;
        *(float4*)&Ks[sg][r][g * 8] = *(const float4*)(Kbase + (long)r * (2 * DIM) + g * 8);
        *(float4*)&Vs[sg][r][g * 8] = *(const float4*)(Vbase + (long)r * (2 * DIM) + g * 8);
    }
    __syncthreads();

    const int a_quad = lane >> 3;
    const int a_rowc = (a_quad & 1) * 8 + (lane & 7);
    const int a_kofs = (a_quad >> 1) * 8;
    const int b_rin  = lane & 7;
    const int b_kofs = ((lane >> 3) & 1) * 8;

    float sacc[4][4];
#pragma unroll
    for (int nt = 0; nt < 4; nt++)
#pragma unroll
        for (int r = 0; r < 4; r++) sacc[nt][r] = 0.0f;

#pragma unroll
    for (int ks = 0; ks < 4; ++ks) {
        const int k0 = ks * 16;
        uint32_t af[4], bf[4][2];
        {
            uint32_t addr = smem_u32(&Qs[sg][wloc * 16 + a_rowc][k0 + a_kofs]);
            asm volatile(
                "ldmatrix.sync.aligned.m8n8.x4.shared.b16 {%0,%1,%2,%3}, [%4];"
                : "=r"(af[0]), "=r"(af[1]), "=r"(af[2]), "=r"(af[3]) : "r"(addr));
        }
#pragma unroll
        for (int nt = 0; nt < 4; ++nt) {
            uint32_t addr = smem_u32(&Ks[sg][nt * 8 + b_rin][k0 + b_kofs]);
            asm volatile(
                "ldmatrix.sync.aligned.m8n8.x2.shared.b16 {%0,%1}, [%2];"
                : "=r"(bf[nt][0]), "=r"(bf[nt][1]) : "r"(addr));
        }
#pragma unroll
        for (int nt = 0; nt < 4; ++nt)
            asm volatile(
                "mma.sync.aligned.m16n8k16.row.col.f32.f16.f16.f32 "
                "{%0,%1,%2,%3}, {%4,%5,%6,%7}, {%8,%9}, {%0,%1,%2,%3};"
                : "+f"(sacc[nt][0]), "+f"(sacc[nt][1]),
                  "+f"(sacc[nt][2]), "+f"(sacc[nt][3])
                : "r"(af[0]), "r"(af[1]), "r"(af[2]), "r"(af[3]),
                  "r"(bf[nt][0]), "r"(bf[nt][1]));
    }

    float mx0 = -1e30f, mx1 = -1e30f;
#pragma unroll
    for (int nt = 0; nt < 4; nt++) {
        mx0 = fmaxf(mx0, fmaxf(sacc[nt][0], sacc[nt][1]));
        mx1 = fmaxf(mx1, fmaxf(sacc[nt][2], sacc[nt][3]));
    }
    mx0 = fmaxf(mx0, __shfl_xor_sync(0xffffffffu, mx0, 1));
    mx0 = fmaxf(mx0, __shfl_xor_sync(0xffffffffu, mx0, 2));
    mx1 = fmaxf(mx1, __shfl_xor_sync(0xffffffffu, mx1, 1));
    mx1 = fmaxf(mx1, __shfl_xor_sync(0xffffffffu, mx1, 2));

    float sum0 = 0.0f, sum1 = 0.0f;
#pragma unroll
    for (int nt = 0; nt < 4; nt++) {
        sacc[nt][0] = __expf(sacc[nt][0] - mx0); sum0 += sacc[nt][0];
        sacc[nt][1] = __expf(sacc[nt][1] - mx0); sum0 += sacc[nt][1];
        sacc[nt][2] = __expf(sacc[nt][2] - mx1); sum1 += sacc[nt][2];
        sacc[nt][3] = __expf(sacc[nt][3] - mx1); sum1 += sacc[nt][3];
    }
    sum0 += __shfl_xor_sync(0xffffffffu, sum0, 1);
    sum0 += __shfl_xor_sync(0xffffffffu, sum0, 2);
    sum1 += __shfl_xor_sync(0xffffffffu, sum1, 1);
    sum1 += __shfl_xor_sync(0xffffffffu, sum1, 2);
    const float inv0 = 1.0f / sum0, inv1 = 1.0f / sum1;

    uint32_t pa[2][4];
#pragma unroll
    for (int j = 0; j < 2; j++) {
        __half2 h0 = __floats2half2_rn(sacc[2 * j][0] * inv0, sacc[2 * j][1] * inv0);
        __half2 h1 = __floats2half2_rn(sacc[2 * j][2] * inv1, sacc[2 * j][3] * inv1);
        __half2 h2_ = __floats2half2_rn(sacc[2 * j + 1][0] * inv0, sacc[2 * j + 1][1] * inv0);
        __half2 h3 = __floats2half2_rn(sacc[2 * j + 1][2] * inv1, sacc[2 * j + 1][3] * inv1);
        pa[j][0] = *(uint32_t*)&h0; pa[j][1] = *(uint32_t*)&h1;
        pa[j][2] = *(uint32_t*)&h2_; pa[j][3] = *(uint32_t*)&h3;
    }

    float oacc[8][4];
#pragma unroll
    for (int nt = 0; nt < 8; nt++)
#pragma unroll
        for (int r = 0; r < 4; r++) oacc[nt][r] = 0.0f;

#pragma unroll
    for (int nt = 0; nt < 8; ++nt) {
        uint32_t vb[4];
        uint32_t addr = smem_u32(&Vs[sg][lane][nt * 8]);
        asm volatile(
            "ldmatrix.sync.aligned.m8n8.x4.trans.shared.b16 {%0,%1,%2,%3}, [%4];"
            : "=r"(vb[0]), "=r"(vb[1]), "=r"(vb[2]), "=r"(vb[3]) : "r"(addr));
#pragma unroll
        for (int j = 0; j < 2; ++j)
            asm volatile(
                "mma.sync.aligned.m16n8k16.row.col.f32.f16.f16.f32 "
                "{%0,%1,%2,%3}, {%4,%5,%6,%7}, {%8,%9}, {%0,%1,%2,%3};"
                : "+f"(oacc[nt][0]), "+f"(oacc[nt][1]),
                  "+f"(oacc[nt][2]), "+f"(oacc[nt][3])
                : "r"(pa[j][0]), "r"(pa[j][1]), "r"(pa[j][2]), "r"(pa[j][3]),
                  "r"(vb[2 * j]), "r"(vb[2 * j + 1]));
    }

    const int r0 = wloc * 16 + gid;
    const int pos0 = hmap[s * SEG + r0];
    const int pos1 = hmap[s * SEG + r0 + 8];
    __half* Op0 = g_Oh + ((long)(b * SEQLEN + pos0)) * DIM + h * HEAD_DIM;
    __half* Op1 = g_Oh + ((long)(b * SEQLEN + pos1)) * DIM + h * HEAD_DIM;
#pragma unroll
    for (int nt = 0; nt < 8; ++nt) {
        __half2 v0 = __floats2half2_rn(oacc[nt][0], oacc[nt][1]);
        __half2 v1 = __floats2half2_rn(oacc[nt][2], oacc[nt][3]);
        *(__half2*)(Op0 + nt * 8 + tidg * 2) = v0;
        *(__half2*)(Op1 + nt * 8 + tidg * 2) = v1;
    }
}

// ---------------- launch ------------------------------------------------------
extern "C" void kernel_launch(void* const* d_in, const int* in_sizes, int n_in,
                              void* d_out, int out_size)
{
    const float* x      = (const float*)d_in[0];
    const float* w_qkv  = (const float*)d_in[1];
    const float* w_proj = (const float*)d_in[2];
    const int*   hmap   = (const int*)  d_in[3];
    float* out = (float*)d_out;

    __half* Xh;  cudaGetSymbolAddress((void**)&Xh,  g_Xh);
    __half* Qh;  cudaGetSymbolAddress((void**)&Qh,  g_Qh);
    __half* KVh; cudaGetSymbolAddress((void**)&KVh, g_KVh);
    __half* Oh;  cudaGetSymbolAddress((void**)&Oh,  g_Oh);
    __half* WqT; cudaGetSymbolAddress((void**)&WqT, g_WqkvT);
    __half* WpT; cudaGetSymbolAddress((void**)&WpT, g_WprojT);
    int* qrow;  cudaGetSymbolAddress((void**)&qrow,  g_qrow);
    int* kvrow; cudaGetSymbolAddress((void**)&kvrow, g_kvrow);

    static bool attr_done = false;
    if (!attr_done) {
        cudaFuncSetAttribute(qkv_gemm_kernel,
                             cudaFuncAttributeMaxDynamicSharedMemorySize, GSMEM);
        cudaFuncSetAttribute(proj_gemm_kernel,
                             cudaFuncAttributeMaxDynamicSharedMemorySize, GSMEM);
        attr_done = true;
    }

    // 1. fused prep: x->fp16 + weight transposes + gather maps (one launch)
    prep_kernel<<<20544, 256>>>(x, w_qkv, w_proj, hmap);

    // 2+3. fused Q (pre-scaled) and KV GEMMs
    qkv_gemm_kernel<<<2048, 256, GSMEM>>>(Xh, WqT, Qh, KVh, qrow, kvrow);

    // 4. tensor-core fused segment attention: 2 segments per CTA
    attn_kernel<<<dim3(NSEG / 2, HEADS, BATCH), 256>>>(hmap);

    // 5. out = O @ w_proj (128x128 tiles, 1024 CTAs)
    proj_gemm_kernel<<<1024, 256, GSMEM>>>(Oh, WpT, out);
}